// round 1
// baseline (speedup 1.0000x reference)
#include <cuda_runtime.h>
#include <cuda_bf16.h>

#define T_ 128
#define B_ 512
#define D_ 500
#define D4_ 125   // D/4 float4 per row

// Scratch (no allocation allowed): control-plane metadata.
__device__ short g_valid_idx[B_ * T_];       // per column: t-index of j-th valid token
__device__ short g_seg_off[B_ * (T_ + 1)];   // per column: exclusive segment ends (in j space)
__device__ int   g_newlen[B_];
__device__ int   g_order[B_];

// ---------------------------------------------------------------------------
// Kernel 1: per-column greedy packing scan (control plane).
// One thread per batch column. Single forward pass: the reference's
// reverse-scan nxt_after formulation is equivalent to "close the current
// segment when the next valid token would overflow token_len" (the last
// valid token always closes a segment since nxt=BIG there).
// ---------------------------------------------------------------------------
__global__ void setup_kernel(const int* __restrict__ src,
                             const int* __restrict__ token_lengths,
                             const int* __restrict__ token_len_p)
{
    int b = blockIdx.x * blockDim.x + threadIdx.x;
    if (b >= B_) return;
    int token_len = token_len_p ? token_len_p[0] : 20;

    short* soff = &g_seg_off[b * (T_ + 1)];
    short* vidx = &g_valid_idx[b * T_];

    int nv = 0, seg = 0, curr = 0;
    soff[0] = 0;
    for (int t = 0; t < T_; t++) {
        int s = src[t * B_ + b];          // coalesced across threads (b contiguous)
        if (s == 1) continue;             // pad token
        int l = (s == 0) ? 4 : token_lengths[s];
        if (curr > 0 && curr + l > token_len) {
            seg++;
            soff[seg] = (short)nv;        // close previous segment
            curr = 0;
        }
        vidx[nv++] = (short)t;
        curr += l;
    }
    if (nv > (int)soff[seg]) {            // close trailing segment (iff any valid token)
        seg++;
        soff[seg] = (short)nv;
    }
    g_newlen[b] = seg;
}

// ---------------------------------------------------------------------------
// Kernel 2: stable descending rank (== jnp.argsort(-new_lengths), stable).
// One block, B_ threads, O(B) per thread. Also emits merged_lengths as fp32.
// ---------------------------------------------------------------------------
__global__ void order_kernel(float* __restrict__ out_len, int write_len)
{
    __shared__ int slen[B_];
    int b = threadIdx.x;
    slen[b] = g_newlen[b];
    __syncthreads();
    int myl = slen[b];
    int rank = 0;
    #pragma unroll 8
    for (int j = 0; j < B_; j++) {
        int lj = slen[j];
        rank += (lj > myl) || (lj == myl && j < b);
    }
    g_order[rank] = b;
    if (write_len) out_len[rank] = (float)myl;
}

// ---------------------------------------------------------------------------
// Kernel 3: data plane. One warp per output row (r, b_out), float4 I/O.
// Row r of output column b_out (source column b = order[b_out]):
//   r <  L : sum of embedded[t, b] over valid tokens t of segment r
//   r >= L : copy of embedded[r, b]
// Consecutive warps -> consecutive b_out at same r -> contiguous writes.
// ---------------------------------------------------------------------------
__global__ void pack_kernel(const float4* __restrict__ embv,
                            float4* __restrict__ outv)
{
    int warp = (blockIdx.x * blockDim.x + threadIdx.x) >> 5;
    int lane = threadIdx.x & 31;
    if (warp >= T_ * B_) return;

    int bo = warp % B_;
    int r  = warp / B_;
    int b  = g_order[bo];
    int L  = g_newlen[b];

    long obase = (long)(r * B_ + bo) * D4_;

    if (r >= L) {
        long ibase = (long)(r * B_ + b) * D4_;
        #pragma unroll
        for (int i = 0; i < 4; i++) {
            int c = lane + 32 * i;
            if (c < D4_) outv[obase + c] = embv[ibase + c];
        }
    } else {
        const short* soff = &g_seg_off[b * (T_ + 1)];
        const short* vidx = &g_valid_idx[b * T_];
        int j0 = soff[r], j1 = soff[r + 1];

        float4 acc[4];
        #pragma unroll
        for (int i = 0; i < 4; i++) acc[i] = make_float4(0.f, 0.f, 0.f, 0.f);

        for (int j = j0; j < j1; j++) {
            int t = vidx[j];
            long ibase = (long)(t * B_ + b) * D4_;
            #pragma unroll
            for (int i = 0; i < 4; i++) {
                int c = lane + 32 * i;
                if (c < D4_) {
                    float4 v = embv[ibase + c];
                    acc[i].x += v.x; acc[i].y += v.y;
                    acc[i].z += v.z; acc[i].w += v.w;
                }
            }
        }
        #pragma unroll
        for (int i = 0; i < 4; i++) {
            int c = lane + 32 * i;
            if (c < D4_) outv[obase + c] = acc[i];
        }
    }
}

// ---------------------------------------------------------------------------
extern "C" void kernel_launch(void* const* d_in, const int* in_sizes, int n_in,
                              void* d_out, int out_size)
{
    const float* emb           = (const float*)d_in[0];   // (T,B,D) fp32
    const int*   src           = (const int*)d_in[1];     // (T,B) int32
    // d_in[2] = lengths (unused by reference computation)
    const int*   token_lengths = (const int*)d_in[3];     // (VOCAB,) int32
    const int*   token_len_p   = (n_in >= 5) ? (const int*)d_in[4] : nullptr;

    float* out = (float*)d_out;
    const long emb_elems = (long)T_ * B_ * D_;
    int write_len = (out_size >= emb_elems + B_) ? 1 : 0;

    setup_kernel<<<(B_ + 127) / 128, 128>>>(src, token_lengths, token_len_p);
    order_kernel<<<1, B_>>>(out + emb_elems, write_len);

    // one warp per output row: T_*B_ warps, 8 warps per 256-thread block
    int total_warps = T_ * B_;
    int blocks = (total_warps * 32 + 255) / 256;
    pack_kernel<<<blocks, 256>>>((const float4*)emb, (float4*)out);
}

// round 2
// speedup vs baseline: 1.8986x; 1.8986x over previous
#include <cuda_runtime.h>
#include <cuda_bf16.h>

#define T_ 128
#define B_ 512
#define D_ 500
#define D4_ 125   // D/4 float4 per row

// Scratch (no allocation allowed): control-plane metadata.
__device__ short g_valid_idx[B_ * T_];       // per column: t-index of j-th valid token
__device__ short g_seg_off[B_ * (T_ + 1)];   // per column: exclusive segment ends (in j space)
__device__ int   g_newlen[B_];
__device__ int   g_order[B_];

// ---------------------------------------------------------------------------
// Kernel 1: per-column greedy packing scan (control plane).
// One BLOCK (128 threads) per batch column: the expensive part (src load +
// random token_lengths gather) runs fully parallel with deep MLP; only the
// trivial integer greedy scan is serialized on lane 0 over shared memory.
// ---------------------------------------------------------------------------
__global__ __launch_bounds__(T_) void setup_kernel(const int* __restrict__ src,
                                                   const int* __restrict__ token_lengths,
                                                   const int* __restrict__ token_len_p)
{
    __shared__ short s_len[T_];      // 0 for pad tokens
    __shared__ short s_vidx[T_];
    __shared__ short s_soff[T_ + 1];
    __shared__ int   s_nseg;

    int b = blockIdx.x;
    int t = threadIdx.x;

    // Parallel gather phase (this was the 82us serial bottleneck before).
    int s = src[t * B_ + b];
    int l = 0;
    if (s != 1) l = (s == 0) ? 4 : token_lengths[s];
    s_len[t] = (short)l;
    __syncthreads();

    // Serial greedy scan on lane 0 (T_=128 tiny int steps over smem).
    if (t == 0) {
        int token_len = token_len_p ? token_len_p[0] : 20;
        int nv = 0, seg = 0, curr = 0;
        s_soff[0] = 0;
        #pragma unroll 4
        for (int tt = 0; tt < T_; tt++) {
            int ll = s_len[tt];
            if (ll == 0) continue;                 // pad
            if (curr > 0 && curr + ll > token_len) {
                seg++;
                s_soff[seg] = (short)nv;
                curr = 0;
            }
            s_vidx[nv++] = (short)tt;
            curr += ll;
        }
        if (nv > (int)s_soff[seg]) {               // close trailing segment
            seg++;
            s_soff[seg] = (short)nv;
        }
        s_nseg = seg;
        g_newlen[b] = seg;
    }
    __syncthreads();

    // Cooperative writeback of metadata.
    g_valid_idx[b * T_ + t] = s_vidx[t];
    if (t <= s_nseg) g_seg_off[b * (T_ + 1) + t] = s_soff[t];
}

// ---------------------------------------------------------------------------
// Kernel 2: stable descending rank (== jnp.argsort(-new_lengths), stable).
// One block, B_ threads, O(B) per thread. Also emits merged_lengths as fp32.
// ---------------------------------------------------------------------------
__global__ void order_kernel(float* __restrict__ out_len, int write_len)
{
    __shared__ int slen[B_];
    int b = threadIdx.x;
    slen[b] = g_newlen[b];
    __syncthreads();
    int myl = slen[b];
    int rank = 0;
    #pragma unroll 8
    for (int j = 0; j < B_; j++) {
        int lj = slen[j];
        rank += (lj > myl) || (lj == myl && j < b);
    }
    g_order[rank] = b;
    if (write_len) out_len[rank] = (float)myl;
}

// ---------------------------------------------------------------------------
// Kernel 3: data plane. One warp per output row (r, b_out), float4 I/O.
// Row r of output column b_out (source column b = order[b_out]):
//   r <  L : sum of embedded[t, b] over valid tokens t of segment r
//   r >= L : copy of embedded[r, b]
// Consecutive warps -> consecutive b_out at same r -> contiguous writes.
// ---------------------------------------------------------------------------
__global__ void pack_kernel(const float4* __restrict__ embv,
                            float4* __restrict__ outv)
{
    int warp = (blockIdx.x * blockDim.x + threadIdx.x) >> 5;
    int lane = threadIdx.x & 31;
    if (warp >= T_ * B_) return;

    int bo = warp % B_;
    int r  = warp / B_;
    int b  = g_order[bo];
    int L  = g_newlen[b];

    long obase = (long)(r * B_ + bo) * D4_;

    if (r >= L) {
        long ibase = (long)(r * B_ + b) * D4_;
        #pragma unroll
        for (int i = 0; i < 4; i++) {
            int c = lane + 32 * i;
            if (c < D4_) outv[obase + c] = embv[ibase + c];
        }
    } else {
        const short* soff = &g_seg_off[b * (T_ + 1)];
        const short* vidx = &g_valid_idx[b * T_];
        int j0 = soff[r], j1 = soff[r + 1];

        float4 acc[4];
        #pragma unroll
        for (int i = 0; i < 4; i++) acc[i] = make_float4(0.f, 0.f, 0.f, 0.f);

        for (int j = j0; j < j1; j++) {
            int t = vidx[j];
            long ibase = (long)(t * B_ + b) * D4_;
            #pragma unroll
            for (int i = 0; i < 4; i++) {
                int c = lane + 32 * i;
                if (c < D4_) {
                    float4 v = embv[ibase + c];
                    acc[i].x += v.x; acc[i].y += v.y;
                    acc[i].z += v.z; acc[i].w += v.w;
                }
            }
        }
        #pragma unroll
        for (int i = 0; i < 4; i++) {
            int c = lane + 32 * i;
            if (c < D4_) outv[obase + c] = acc[i];
        }
    }
}

// ---------------------------------------------------------------------------
extern "C" void kernel_launch(void* const* d_in, const int* in_sizes, int n_in,
                              void* d_out, int out_size)
{
    const float* emb           = (const float*)d_in[0];   // (T,B,D) fp32
    const int*   src           = (const int*)d_in[1];     // (T,B) int32
    // d_in[2] = lengths (unused by reference computation)
    const int*   token_lengths = (const int*)d_in[3];     // (VOCAB,) int32
    const int*   token_len_p   = (n_in >= 5) ? (const int*)d_in[4] : nullptr;

    float* out = (float*)d_out;
    const long emb_elems = (long)T_ * B_ * D_;
    int write_len = (out_size >= emb_elems + B_) ? 1 : 0;

    setup_kernel<<<B_, T_>>>(src, token_lengths, token_len_p);
    order_kernel<<<1, B_>>>(out + emb_elems, write_len);

    // one warp per output row: T_*B_ warps, 8 warps per 256-thread block
    int total_warps = T_ * B_;
    int blocks = (total_warps * 32 + 255) / 256;
    pack_kernel<<<blocks, 256>>>((const float4*)emb, (float4*)out);
}

// round 3
// speedup vs baseline: 1.9862x; 1.0461x over previous
#include <cuda_runtime.h>
#include <cuda_bf16.h>

#define T_ 128
#define B_ 512
#define D_ 500
#define D4_ 125   // D/4 float4 per row

// Scratch (no allocation allowed): control-plane metadata.
__device__ short g_valid_idx[B_ * T_];       // per column: t-index of j-th valid token
__device__ short g_seg_off[B_ * (T_ + 1)];   // per column: exclusive segment ends (in j space)
__device__ int   g_newlen[B_];
__device__ int   g_order[B_];

// ---------------------------------------------------------------------------
// Kernel 1: per-column greedy packing scan (control plane).
// One block (128 threads) per batch column. Threads gather token lengths in
// parallel (hides DRAM/L2 latency), deposit them as BYTES in shared; lane 0
// bulk-loads them with 8x LDS.128 into registers and runs the 128-step greedy
// scan as pure register ALU (no per-step LDS latency chain).
// ---------------------------------------------------------------------------
__global__ __launch_bounds__(T_) void setup_kernel(const int* __restrict__ src,
                                                   const int* __restrict__ token_lengths,
                                                   const int* __restrict__ token_len_p)
{
    __shared__ uint4 s_len4[T_ / 16];          // 128 bytes of lengths
    __shared__ short s_vidx[T_];
    __shared__ short s_soff[T_ + 1];
    __shared__ int   s_nseg;

    int b = blockIdx.x;
    int t = threadIdx.x;

    // Parallel gather phase.
    int s = src[t * B_ + b];
    int l = (s == 1) ? 0 : ((s == 0) ? 4 : token_lengths[s]);
    ((unsigned char*)s_len4)[t] = (unsigned char)l;
    s_vidx[t] = 0;
    __syncthreads();

    if (t == 0) {
        int token_len = token_len_p ? token_len_p[0] : 20;

        // Bulk-load all 128 length bytes into registers (8x LDS.128).
        uint w[T_ / 4];
        #pragma unroll
        for (int i = 0; i < T_ / 16; i++) {
            uint4 v = s_len4[i];
            w[i * 4 + 0] = v.x; w[i * 4 + 1] = v.y;
            w[i * 4 + 2] = v.z; w[i * 4 + 3] = v.w;
        }

        // Fully-unrolled register-resident greedy scan.
        int nv = 0, seg = 0, curr = 0;
        s_soff[0] = 0;
        #pragma unroll
        for (int tt = 0; tt < T_; tt++) {
            int ll = (w[tt >> 2] >> ((tt & 3) * 8)) & 0xFF;
            if (ll != 0) {
                if (curr > 0 && curr + ll > token_len) {
                    seg++;
                    s_soff[seg] = (short)nv;
                    curr = 0;
                }
                s_vidx[nv++] = (short)tt;
                curr += ll;
            }
        }
        if (nv > (int)s_soff[seg]) {           // close trailing segment
            seg++;
            s_soff[seg] = (short)nv;
        }
        s_nseg = seg;
        g_newlen[b] = seg;
    }
    __syncthreads();

    // Cooperative writeback of metadata.
    g_valid_idx[b * T_ + t] = s_vidx[t];
    if (t <= s_nseg) g_seg_off[b * (T_ + 1) + t] = s_soff[t];
}

// ---------------------------------------------------------------------------
// Kernel 2: stable descending rank (== jnp.argsort(-new_lengths), stable).
// One block, B_ threads, O(B) per thread. Also emits merged_lengths as fp32.
// ---------------------------------------------------------------------------
__global__ void order_kernel(float* __restrict__ out_len, int write_len)
{
    __shared__ int slen[B_];
    int b = threadIdx.x;
    slen[b] = g_newlen[b];
    __syncthreads();
    int myl = slen[b];
    int rank = 0;
    #pragma unroll 16
    for (int j = 0; j < B_; j++) {
        int lj = slen[j];
        rank += (lj > myl) || (lj == myl && j < b);
    }
    g_order[rank] = b;
    if (write_len) out_len[rank] = (float)myl;
}

// ---------------------------------------------------------------------------
// Kernel 3: data plane. One warp per output row (r, b_out), float4 I/O.
// Row r of output column b_out (source column b = order[b_out]):
//   r <  L : sum of embedded[t, b] over valid tokens t of segment r
//   r >= L : copy of embedded[r, b]
// Consecutive warps -> consecutive b_out at same r -> contiguous writes.
// ---------------------------------------------------------------------------
__global__ void pack_kernel(const float4* __restrict__ embv,
                            float4* __restrict__ outv)
{
    int warp = (blockIdx.x * blockDim.x + threadIdx.x) >> 5;
    int lane = threadIdx.x & 31;
    if (warp >= T_ * B_) return;

    int bo = warp % B_;
    int r  = warp / B_;
    int b  = g_order[bo];
    int L  = g_newlen[b];

    long obase = (long)(r * B_ + bo) * D4_;

    if (r >= L) {
        long ibase = (long)(r * B_ + b) * D4_;
        #pragma unroll
        for (int i = 0; i < 4; i++) {
            int c = lane + 32 * i;
            if (c < D4_) outv[obase + c] = embv[ibase + c];
        }
    } else {
        const short* soff = &g_seg_off[b * (T_ + 1)];
        const short* vidx = &g_valid_idx[b * T_];
        int j0 = soff[r], j1 = soff[r + 1];

        float4 acc[4];
        #pragma unroll
        for (int i = 0; i < 4; i++) acc[i] = make_float4(0.f, 0.f, 0.f, 0.f);

        for (int j = j0; j < j1; j++) {
            int t = vidx[j];
            long ibase = (long)(t * B_ + b) * D4_;
            #pragma unroll
            for (int i = 0; i < 4; i++) {
                int c = lane + 32 * i;
                if (c < D4_) {
                    float4 v = embv[ibase + c];
                    acc[i].x += v.x; acc[i].y += v.y;
                    acc[i].z += v.z; acc[i].w += v.w;
                }
            }
        }
        #pragma unroll
        for (int i = 0; i < 4; i++) {
            int c = lane + 32 * i;
            if (c < D4_) outv[obase + c] = acc[i];
        }
    }
}

// ---------------------------------------------------------------------------
extern "C" void kernel_launch(void* const* d_in, const int* in_sizes, int n_in,
                              void* d_out, int out_size)
{
    const float* emb           = (const float*)d_in[0];   // (T,B,D) fp32
    const int*   src           = (const int*)d_in[1];     // (T,B) int32
    // d_in[2] = lengths (unused by reference computation)
    const int*   token_lengths = (const int*)d_in[3];     // (VOCAB,) int32
    const int*   token_len_p   = (n_in >= 5) ? (const int*)d_in[4] : nullptr;

    float* out = (float*)d_out;
    const long emb_elems = (long)T_ * B_ * D_;
    int write_len = (out_size >= emb_elems + B_) ? 1 : 0;

    setup_kernel<<<B_, T_>>>(src, token_lengths, token_len_p);
    order_kernel<<<1, B_>>>(out + emb_elems, write_len);

    // one warp per output row: T_*B_ warps, 8 warps per 256-thread block
    int total_warps = T_ * B_;
    int blocks = (total_warps * 32 + 255) / 256;
    pack_kernel<<<blocks, 256>>>((const float4*)emb, (float4*)out);
}

// round 4
// speedup vs baseline: 2.1943x; 1.1048x over previous
#include <cuda_runtime.h>
#include <cuda_bf16.h>

#define T_ 128
#define B_ 512
#define D_ 500
#define D4_ 125   // D/4 float4 per row

// Scratch (no allocation allowed): control-plane metadata.
__device__ short g_valid_idx[B_ * T_];       // per column: t-index of j-th valid token
__device__ short g_seg_off[B_ * (T_ + 1)];   // per column: exclusive segment ends (in j space)
__device__ int   g_newlen[B_];
__device__ int   g_order[B_];

// ---------------------------------------------------------------------------
// Kernel 1: per-column greedy packing scan (control plane).
// One block (128 threads) per batch column. Threads gather token lengths in
// parallel; lane 0 bulk-loads them into registers and runs a BRANCHLESS
// (predication-friendly) 128-step greedy scan: no BSSY/BSYNC envelopes,
// only predicated shared stores + select/ALU per step.
// ---------------------------------------------------------------------------
__global__ __launch_bounds__(T_) void setup_kernel(const int* __restrict__ src,
                                                   const int* __restrict__ token_lengths,
                                                   const int* __restrict__ token_len_p)
{
    __shared__ uint4 s_len4[T_ / 16];          // 128 bytes of lengths
    __shared__ short s_vidx[T_];
    __shared__ short s_soff[T_ + 2];
    __shared__ int   s_nseg;

    int b = blockIdx.x;
    int t = threadIdx.x;

    // Parallel gather phase.
    int s = src[t * B_ + b];
    int l = (s == 1) ? 0 : ((s == 0) ? 4 : token_lengths[s]);
    ((unsigned char*)s_len4)[t] = (unsigned char)l;
    s_vidx[t] = 0;
    __syncthreads();

    if (t == 0) {
        int token_len = token_len_p ? token_len_p[0] : 20;

        // Bulk-load all 128 length bytes into registers (8x LDS.128).
        uint w[T_ / 4];
        #pragma unroll
        for (int i = 0; i < T_ / 16; i++) {
            uint4 v = s_len4[i];
            w[i * 4 + 0] = v.x; w[i * 4 + 1] = v.y;
            w[i * 4 + 2] = v.z; w[i * 4 + 3] = v.w;
        }

        // Branchless register-resident greedy scan (predicated stores only).
        int nv = 0, seg = 0, curr = 0;
        s_soff[0] = 0;
        #pragma unroll
        for (int tt = 0; tt < T_; tt++) {
            int ll = (w[tt >> 2] >> ((tt & 3) * 8)) & 0xFF;
            bool valid = (ll != 0);
            bool close = valid & (curr > 0) & (curr + ll > token_len);
            if (close) s_soff[seg + 1] = (short)nv;   // predicated STS
            seg  += (int)close;
            curr  = close ? 0 : curr;
            if (valid) s_vidx[nv] = (short)tt;        // predicated STS
            nv   += (int)valid;
            curr += valid ? ll : 0;
        }
        bool trail = (nv > (int)s_soff[seg]);
        if (trail) s_soff[seg + 1] = (short)nv;
        seg += (int)trail;
        s_nseg = seg;
        g_newlen[b] = seg;
    }
    __syncthreads();

    // Cooperative writeback of metadata.
    g_valid_idx[b * T_ + t] = s_vidx[t];
    if (t <= s_nseg) g_seg_off[b * (T_ + 1) + t] = s_soff[t];
}

// ---------------------------------------------------------------------------
// Kernel 2: stable descending rank (== jnp.argsort(-new_lengths), stable).
// Grid-parallel: one 128-thread block per column b. Each thread handles 4
// entries (int4 load), block-reduces the predicate count, thread 0 scatters.
// ---------------------------------------------------------------------------
__global__ __launch_bounds__(128) void order_kernel(float* __restrict__ out_len,
                                                    int write_len)
{
    __shared__ int s_warp[4];
    int b = blockIdx.x;
    int t = threadIdx.x;
    int myl = g_newlen[b];

    const int4* len4 = (const int4*)g_newlen;
    int4 v = len4[t];                  // j = 4t .. 4t+3
    int j = 4 * t;
    int cnt = 0;
    cnt += (v.x > myl) || (v.x == myl && (j + 0) < b);
    cnt += (v.y > myl) || (v.y == myl && (j + 1) < b);
    cnt += (v.z > myl) || (v.z == myl && (j + 2) < b);
    cnt += (v.w > myl) || (v.w == myl && (j + 3) < b);

    // warp reduce
    #pragma unroll
    for (int o = 16; o > 0; o >>= 1) cnt += __shfl_down_sync(0xFFFFFFFFu, cnt, o);
    if ((t & 31) == 0) s_warp[t >> 5] = cnt;
    __syncthreads();
    if (t == 0) {
        int rank = s_warp[0] + s_warp[1] + s_warp[2] + s_warp[3];
        g_order[rank] = b;
        if (write_len) out_len[rank] = (float)myl;
    }
}

// ---------------------------------------------------------------------------
// Kernel 3: data plane. One warp per output row (r, b_out), float4 I/O.
// Row r of output column b_out (source column b = order[b_out]):
//   r <  L : sum of embedded[t, b] over valid tokens t of segment r
//   r >= L : copy of embedded[r, b]
// Consecutive warps -> consecutive b_out at same r -> contiguous writes.
// ---------------------------------------------------------------------------
__global__ void pack_kernel(const float4* __restrict__ embv,
                            float4* __restrict__ outv)
{
    int warp = (blockIdx.x * blockDim.x + threadIdx.x) >> 5;
    int lane = threadIdx.x & 31;
    if (warp >= T_ * B_) return;

    int bo = warp % B_;
    int r  = warp / B_;
    int b  = g_order[bo];
    int L  = g_newlen[b];

    long obase = (long)(r * B_ + bo) * D4_;

    if (r >= L) {
        long ibase = (long)(r * B_ + b) * D4_;
        #pragma unroll
        for (int i = 0; i < 4; i++) {
            int c = lane + 32 * i;
            if (c < D4_) outv[obase + c] = embv[ibase + c];
        }
    } else {
        const short* soff = &g_seg_off[b * (T_ + 1)];
        const short* vidx = &g_valid_idx[b * T_];
        int j0 = soff[r], j1 = soff[r + 1];

        float4 acc[4];
        #pragma unroll
        for (int i = 0; i < 4; i++) acc[i] = make_float4(0.f, 0.f, 0.f, 0.f);

        for (int j = j0; j < j1; j++) {
            int t = vidx[j];
            long ibase = (long)(t * B_ + b) * D4_;
            #pragma unroll
            for (int i = 0; i < 4; i++) {
                int c = lane + 32 * i;
                if (c < D4_) {
                    float4 v = embv[ibase + c];
                    acc[i].x += v.x; acc[i].y += v.y;
                    acc[i].z += v.z; acc[i].w += v.w;
                }
            }
        }
        #pragma unroll
        for (int i = 0; i < 4; i++) {
            int c = lane + 32 * i;
            if (c < D4_) outv[obase + c] = acc[i];
        }
    }
}

// ---------------------------------------------------------------------------
extern "C" void kernel_launch(void* const* d_in, const int* in_sizes, int n_in,
                              void* d_out, int out_size)
{
    const float* emb           = (const float*)d_in[0];   // (T,B,D) fp32
    const int*   src           = (const int*)d_in[1];     // (T,B) int32
    // d_in[2] = lengths (unused by reference computation)
    const int*   token_lengths = (const int*)d_in[3];     // (VOCAB,) int32
    const int*   token_len_p   = (n_in >= 5) ? (const int*)d_in[4] : nullptr;

    float* out = (float*)d_out;
    const long emb_elems = (long)T_ * B_ * D_;
    int write_len = (out_size >= emb_elems + B_) ? 1 : 0;

    setup_kernel<<<B_, T_>>>(src, token_lengths, token_len_p);
    order_kernel<<<B_, 128>>>(out + emb_elems, write_len);

    // one warp per output row: T_*B_ warps, 8 warps per 256-thread block
    int total_warps = T_ * B_;
    int blocks = (total_warps * 32 + 255) / 256;
    pack_kernel<<<blocks, 256>>>((const float4*)emb, (float4*)out);
}